// round 15
// baseline (speedup 1.0000x reference)
#include <cuda_runtime.h>
#include <cuda_fp16.h>
#include <mma.h>

using namespace nvcuda;

// ---------------------------------------------------------------------------
// GAT (2-layer, PyG-style) on B200 (sm_100a). Pristine module form; total
// __device__ data ~12.2 MB. Layer-2 GEMM folded through the segment-sum.
//
// R15 vs R14 (212.7 us):
//  * CSR build collapsed 5 kernels -> 2: k_count + one fused single-block
//    scan kernel (serial-per-thread 2-sweep scan, warp-shuffle block scan,
//    re-zeros g_deg for replay determinism, computes vs/vd on the side).
//  * Edge loops load 4 CSR indices per LDG.64 (aligned ushort4) with scalar
//    peeling, cutting index-load issue pressure 4x.
// Launches: count, scan_fused, scatter, gemm1, edge1, edge2 (6 total).
// ---------------------------------------------------------------------------

#define NNODES 50000
#define NEDGES 1600000
#define SLOPE  0.2f
#define EPSV   1e-16f

// ------------------------- scratch (static device) --------------------------
__device__ unsigned short g_csr[NEDGES];        // 3.2 MB
__device__ __half2        g_a1[NNODES * 8];     // (as,ad) per head, 1.6 MB
__device__ __half2        g_hin[NNODES * 32];   // hin fp16 [N,64], 6.4 MB
__device__ float          g_as2[NNODES];        // 0.2 MB
__device__ float          g_ad2[NNODES];        // 0.2 MB
__device__ int            g_row_ptr[NNODES + 1];
__device__ int            g_deg[NNODES];        // zero at load; re-zeroed each run
__device__ int            g_pos[NNODES];
__device__ float          g_vs[64];
__device__ float          g_vd[64];

__device__ __forceinline__ float lrelu(float v) { return fmaxf(v, SLOPE * v); }

// ------------------------------ CSR build -----------------------------------
__global__ void __launch_bounds__(256) k_count(const int* __restrict__ dst, int n) {
    int e = blockIdx.x * blockDim.x + threadIdx.x;
    if (e < n) atomicAdd(&g_deg[dst[e]], 1);
}

// One-block fused kernel: exclusive scan of g_deg -> row_ptr/pos (two-sweep,
// no per-thread arrays), re-zero g_deg, and compute vs/vd = W2 @ att2 vecs.
#define SCAN_T 1024
#define PER_T  49              // 1024*49 = 50176 >= NNODES
__global__ void __launch_bounds__(SCAN_T) k_scan_fused(
    const float* __restrict__ W2,
    const float* __restrict__ att_src2,
    const float* __restrict__ att_dst2) {
    const int t = threadIdx.x;
    const int base = t * PER_T;

    // sweep 1: per-thread sum
    int sum = 0;
    for (int j = 0; j < PER_T; j++) {
        int idx = base + j;
        if (idx < NNODES) sum += g_deg[idx];
    }
    // block exclusive scan of sums (warp shuffle + smem)
    const int lane = t & 31, wid = t >> 5;
    int v = sum;
#pragma unroll
    for (int off = 1; off < 32; off <<= 1) {
        int u = __shfl_up_sync(0xffffffffu, v, off);
        if (lane >= off) v += u;
    }
    __shared__ int wsum[32];
    if (lane == 31) wsum[wid] = v;
    __syncthreads();
    if (wid == 0) {
        int wv = wsum[lane];
#pragma unroll
        for (int off = 1; off < 32; off <<= 1) {
            int u = __shfl_up_sync(0xffffffffu, wv, off);
            if (lane >= off) wv += u;
        }
        wsum[lane] = wv;
    }
    __syncthreads();
    int run = (v - sum) + (wid ? wsum[wid - 1] : 0);

    // sweep 2: write prefixes, re-zero deg
    for (int j = 0; j < PER_T; j++) {
        int idx = base + j;
        if (idx < NNODES) {
            int d = g_deg[idx];
            g_row_ptr[idx] = run;
            g_pos[idx] = run;
            run += d;
            g_deg[idx] = 0;
        }
    }
    if (t == 0) g_row_ptr[NNODES] = NEDGES;

    // side job: vs/vd (threads 0..63)
    if (t < 64) {
        float vs = 0.f, vd = 0.f;
        for (int j = 0; j < 64; j++) {
            float w = W2[t * 64 + j];
            vs += w * att_src2[j];
            vd += w * att_dst2[j];
        }
        g_vs[t] = vs;
        g_vd[t] = vd;
    }
}

__global__ void __launch_bounds__(256) k_scatter(const int* __restrict__ src,
                                                 const int* __restrict__ dst, int n) {
    int e = blockIdx.x * blockDim.x + threadIdx.x;
    if (e < n) {
        int d = dst[e];
        int p = atomicAdd(&g_pos[d], 1);
        g_csr[p] = (unsigned short)src[e];
    }
}

// --------------- GEMM1 (wmma fp16 tensor cores) + fused att1 -----------------
struct GemmAB {
    __half As[128][40];     // 128x32 + pad8
    __half Bs[32][72];      // 32x64 + pad8
};
union GemmSmem {
    GemmAB ab;
    float  Cs[128][68];     // 128x64 + pad4
};

__global__ void __launch_bounds__(256) k_gemm1(const float* __restrict__ A,
                                               const float* __restrict__ B,
                                               const float* __restrict__ att_src,
                                               const float* __restrict__ att_dst,
                                               __half2* __restrict__ C, int M) {
    const int block_row = blockIdx.x * 128;
    if (block_row >= M) return;
    __shared__ GemmSmem sm;
    __shared__ float ss[64], sd[64];
    const int tid = threadIdx.x;
    if (tid < 64) { ss[tid] = att_src[tid]; sd[tid] = att_dst[tid]; }

    const int wid = tid >> 5;
    const int warp_m = wid & 3;
    const int warp_n = wid >> 2;

    wmma::fragment<wmma::accumulator, 16, 16, 16, float> acc[2][2];
#pragma unroll
    for (int i = 0; i < 2; i++)
#pragma unroll
        for (int j = 0; j < 2; j++) wmma::fill_fragment(acc[i][j], 0.f);

    for (int k0 = 0; k0 < 256; k0 += 32) {
#pragma unroll
        for (int it = 0; it < 4; it++) {
            int f4 = it * 256 + tid;
            int r = f4 >> 3;
            int c4 = (f4 & 7) * 4;
            int gr = block_row + r;
            float4 v = make_float4(0.f, 0.f, 0.f, 0.f);
            if (gr < M) v = *(const float4*)(A + (size_t)gr * 256 + k0 + c4);
            sm.ab.As[r][c4 + 0] = __float2half_rn(v.x);
            sm.ab.As[r][c4 + 1] = __float2half_rn(v.y);
            sm.ab.As[r][c4 + 2] = __float2half_rn(v.z);
            sm.ab.As[r][c4 + 3] = __float2half_rn(v.w);
        }
#pragma unroll
        for (int it = 0; it < 2; it++) {
            int f4 = it * 256 + tid;
            int r = f4 >> 4;
            int c4 = (f4 & 15) * 4;
            float4 v = *(const float4*)(B + (size_t)(k0 + r) * 64 + c4);
            sm.ab.Bs[r][c4 + 0] = __float2half_rn(v.x);
            sm.ab.Bs[r][c4 + 1] = __float2half_rn(v.y);
            sm.ab.Bs[r][c4 + 2] = __float2half_rn(v.z);
            sm.ab.Bs[r][c4 + 3] = __float2half_rn(v.w);
        }
        __syncthreads();
#pragma unroll
        for (int kf = 0; kf < 2; kf++) {
            wmma::fragment<wmma::matrix_a, 16, 16, 16, __half, wmma::row_major> a_frag[2];
            wmma::fragment<wmma::matrix_b, 16, 16, 16, __half, wmma::row_major> b_frag[2];
#pragma unroll
            for (int fm = 0; fm < 2; fm++)
                wmma::load_matrix_sync(a_frag[fm],
                    &sm.ab.As[warp_m * 32 + fm * 16][kf * 16], 40);
#pragma unroll
            for (int fn = 0; fn < 2; fn++)
                wmma::load_matrix_sync(b_frag[fn],
                    &sm.ab.Bs[kf * 16][warp_n * 32 + fn * 16], 72);
#pragma unroll
            for (int fm = 0; fm < 2; fm++)
#pragma unroll
                for (int fn = 0; fn < 2; fn++)
                    wmma::mma_sync(acc[fm][fn], a_frag[fm], b_frag[fn], acc[fm][fn]);
        }
        __syncthreads();
    }

#pragma unroll
    for (int fm = 0; fm < 2; fm++)
#pragma unroll
        for (int fn = 0; fn < 2; fn++)
            wmma::store_matrix_sync(&sm.Cs[warp_m * 32 + fm * 16][warp_n * 32 + fn * 16],
                                    acc[fm][fn], 68, wmma::mem_row_major);
    __syncthreads();

    if (tid < 128) {
        int gr = block_row + tid;
        if (gr < M) {
            const float* row = sm.Cs[tid];
#pragma unroll
            for (int c = 0; c < 32; c++)
                C[(size_t)gr * 32 + c] = __floats2half2_rn(row[2 * c], row[2 * c + 1]);
#pragma unroll
            for (int h = 0; h < 8; h++) {
                float as = 0.f, ad = 0.f;
#pragma unroll
                for (int j = 0; j < 8; j++) {
                    float v = row[h * 8 + j];
                    as += v * ss[h * 8 + j];
                    ad += v * sd[h * 8 + j];
                }
                g_a1[(size_t)gr * 8 + h] = __floats2half2_rn(as, ad);
            }
        }
    }
}

// ------- layer 1: ONE-pass softmax-agg + ELU + fused layer-2 att dots -------
// warp per node; lane owns features 2*lane, 2*lane+1 (head = lane>>2).
// CSR indices loaded 4-at-a-time via aligned ushort4 with scalar peeling.
__global__ void __launch_bounds__(256) k_edge1(const __half2* __restrict__ h1,
                                               const float* __restrict__ b1, int n) {
    int wid = (blockIdx.x * blockDim.x + threadIdx.x) >> 5;
    int lane = threadIdx.x & 31;
    if (wid >= n) return;
    const int d = wid;
    const int beg = g_row_ptr[d];
    const int end = g_row_ptr[d + 1];
    const int h0 = lane >> 2;
    const int f0 = 2 * lane;

    float2 pd = __half22float2(g_a1[(size_t)d * 8 + h0]);
    const float ad_h = pd.y;
    const float aself = lrelu(pd.x + ad_h);

    float acc0 = 0.f, acc1 = 0.f, sden = 0.f;
    int e = beg;
    {   // peel to 4-alignment
        int pre = (4 - (beg & 3)) & 3;
        int stop = beg + pre;
        if (stop > end) stop = end;
        for (; e < stop; e++) {
            int s = g_csr[e];
            float2 pa = __half22float2(g_a1[(size_t)s * 8 + h0]);
            float w = __expf(lrelu(pa.x + ad_h));
            sden += w;
            float2 hv = __half22float2(h1[(size_t)s * 32 + lane]);
            acc0 += hv.x * w;
            acc1 += hv.y * w;
        }
    }
    for (; e + 4 <= end; e += 4) {
        ushort4 s4 = *(const ushort4*)&g_csr[e];
        int s0 = s4.x, s1 = s4.y, s2 = s4.z, s3 = s4.w;
        float2 pa0 = __half22float2(g_a1[(size_t)s0 * 8 + h0]);
        float2 pa1 = __half22float2(g_a1[(size_t)s1 * 8 + h0]);
        float2 pa2 = __half22float2(g_a1[(size_t)s2 * 8 + h0]);
        float2 pa3 = __half22float2(g_a1[(size_t)s3 * 8 + h0]);
        float2 hv0 = __half22float2(h1[(size_t)s0 * 32 + lane]);
        float2 hv1 = __half22float2(h1[(size_t)s1 * 32 + lane]);
        float2 hv2 = __half22float2(h1[(size_t)s2 * 32 + lane]);
        float2 hv3 = __half22float2(h1[(size_t)s3 * 32 + lane]);
        float w0 = __expf(lrelu(pa0.x + ad_h));
        float w1 = __expf(lrelu(pa1.x + ad_h));
        float w2 = __expf(lrelu(pa2.x + ad_h));
        float w3 = __expf(lrelu(pa3.x + ad_h));
        sden += (w0 + w1) + (w2 + w3);
        acc0 += hv0.x * w0 + hv1.x * w1 + hv2.x * w2 + hv3.x * w3;
        acc1 += hv0.y * w0 + hv1.y * w1 + hv2.y * w2 + hv3.y * w3;
    }
    for (; e < end; e++) {
        int s = g_csr[e];
        float2 pa = __half22float2(g_a1[(size_t)s * 8 + h0]);
        float w = __expf(lrelu(pa.x + ad_h));
        sden += w;
        float2 hv = __half22float2(h1[(size_t)s * 32 + lane]);
        acc0 += hv.x * w;
        acc1 += hv.y * w;
    }
    {   // self loop
        float w = __expf(aself);
        sden += w;
        float2 hv = __half22float2(h1[(size_t)d * 32 + lane]);
        acc0 += hv.x * w;
        acc1 += hv.y * w;
    }
    float rinv = 1.f / (sden + EPSV);
    float2 bb = *(const float2*)(b1 + f0);
    float v0 = acc0 * rinv + bb.x;
    float v1 = acc1 * rinv + bb.y;
    v0 = (v0 > 0.f) ? v0 : (__expf(v0) - 1.f);   // ELU
    v1 = (v1 > 0.f) ? v1 : (__expf(v1) - 1.f);
    g_hin[(size_t)d * 32 + lane] = __floats2half2_rn(v0, v1);

    float ps = v0 * g_vs[f0] + v1 * g_vs[f0 + 1];
    float pdd = v0 * g_vd[f0] + v1 * g_vd[f0 + 1];
#pragma unroll
    for (int off = 16; off; off >>= 1) {
        ps  += __shfl_xor_sync(0xffffffffu, ps, off);
        pdd += __shfl_xor_sync(0xffffffffu, pdd, off);
    }
    if (lane == 0) {
        g_as2[d] = ps;
        g_ad2[d] = pdd;
    }
}

// -- layer 2: ONE-pass softmax-agg over hin, fused @W2 + b2 + log_softmax ----
__global__ void __launch_bounds__(256) k_edge2(const float* __restrict__ W2,
                                               const float* __restrict__ b2,
                                               float* __restrict__ out, int n) {
    __shared__ float2 W2s[64 * 32];
    __shared__ float  b2s[64];
    __shared__ float  sagg[8][64];
    int tid = threadIdx.x;
    {
        const float2* w2v = (const float2*)W2;
#pragma unroll
        for (int it = 0; it < 8; it++) W2s[tid + it * 256] = w2v[tid + it * 256];
        if (tid < 64) b2s[tid] = b2[tid];
    }
    __syncthreads();

    int wid = (blockIdx.x * blockDim.x + tid) >> 5;
    int wloc = (tid >> 5);
    int lane = tid & 31;
    if (wid >= n) return;
    const int d = wid;
    const int beg = g_row_ptr[d];
    const int end = g_row_ptr[d + 1];
    const float ad2 = g_ad2[d];
    const float aself = lrelu(g_as2[d] + ad2);

    float acc0 = 0.f, acc1 = 0.f, sden = 0.f;
    int e = beg;
    {   // peel to 4-alignment
        int pre = (4 - (beg & 3)) & 3;
        int stop = beg + pre;
        if (stop > end) stop = end;
        for (; e < stop; e++) {
            int s = g_csr[e];
            float w = __expf(lrelu(g_as2[s] + ad2));
            sden += w;
            float2 f = __half22float2(g_hin[(size_t)s * 32 + lane]);
            acc0 += f.x * w;
            acc1 += f.y * w;
        }
    }
    for (; e + 4 <= end; e += 4) {
        ushort4 s4 = *(const ushort4*)&g_csr[e];
        int s0 = s4.x, s1 = s4.y, s2 = s4.z, s3 = s4.w;
        float a0 = g_as2[s0], a1 = g_as2[s1], a2 = g_as2[s2], a3 = g_as2[s3];
        float2 f0v = __half22float2(g_hin[(size_t)s0 * 32 + lane]);
        float2 f1v = __half22float2(g_hin[(size_t)s1 * 32 + lane]);
        float2 f2v = __half22float2(g_hin[(size_t)s2 * 32 + lane]);
        float2 f3v = __half22float2(g_hin[(size_t)s3 * 32 + lane]);
        float w0 = __expf(lrelu(a0 + ad2));
        float w1 = __expf(lrelu(a1 + ad2));
        float w2 = __expf(lrelu(a2 + ad2));
        float w3 = __expf(lrelu(a3 + ad2));
        sden += (w0 + w1) + (w2 + w3);
        acc0 += f0v.x * w0 + f1v.x * w1 + f2v.x * w2 + f3v.x * w3;
        acc1 += f0v.y * w0 + f1v.y * w1 + f2v.y * w2 + f3v.y * w3;
    }
    for (; e < end; e++) {
        int s = g_csr[e];
        float w = __expf(lrelu(g_as2[s] + ad2));
        sden += w;
        float2 f = __half22float2(g_hin[(size_t)s * 32 + lane]);
        acc0 += f.x * w;
        acc1 += f.y * w;
    }
    {
        float w = __expf(aself);
        sden += w;
        float2 f = __half22float2(g_hin[(size_t)d * 32 + lane]);
        acc0 += f.x * w;
        acc1 += f.y * w;
    }
    float rinv = 1.f / (sden + EPSV);
    acc0 *= rinv;
    acc1 *= rinv;

    sagg[wloc][2 * lane]     = acc0;
    sagg[wloc][2 * lane + 1] = acc1;
    __syncwarp();
    float o0 = b2s[2 * lane];
    float o1 = b2s[2 * lane + 1];
#pragma unroll
    for (int k = 0; k < 64; k++) {
        float a = sagg[wloc][k];
        float2 w2 = W2s[k * 32 + lane];
        o0 += a * w2.x;
        o1 += a * w2.y;
    }

    float mx = fmaxf(o0, o1);
#pragma unroll
    for (int off = 16; off; off >>= 1)
        mx = fmaxf(mx, __shfl_xor_sync(0xffffffffu, mx, off));
    float se = __expf(o0 - mx) + __expf(o1 - mx);
#pragma unroll
    for (int off = 16; off; off >>= 1)
        se += __shfl_xor_sync(0xffffffffu, se, off);
    float l = mx + logf(se);
    float2* out2 = (float2*)(out + (size_t)d * 64);
    out2[lane] = make_float2(o0 - l, o1 - l);
}

// ------------------------------ launcher ------------------------------------
extern "C" void kernel_launch(void* const* d_in, const int* in_sizes, int n_in,
                              void* d_out, int out_size) {
    const float* x        = (const float*)d_in[0];
    const int*   ei       = (const int*)d_in[1];
    const float* W1       = (const float*)d_in[2];
    const float* att_src1 = (const float*)d_in[3];
    const float* att_dst1 = (const float*)d_in[4];
    const float* b1       = (const float*)d_in[5];
    const float* W2       = (const float*)d_in[6];
    const float* att_src2 = (const float*)d_in[7];
    const float* att_dst2 = (const float*)d_in[8];
    const float* b2       = (const float*)d_in[9];
    float* out = (float*)d_out;

    const int* src = ei;
    const int* dst = ei + NEDGES;

    // CSR build (2 kernels; g_deg re-zeroed inside k_scan_fused)
    k_count<<<(NEDGES + 255) / 256, 256>>>(dst, NEDGES);
    k_scan_fused<<<1, SCAN_T>>>(W2, att_src2, att_dst2);
    k_scatter<<<(NEDGES + 255) / 256, 256>>>(src, dst, NEDGES);

    // layer 1: h1(fp16) -> d_out, att1 dots fused -> g_a1
    k_gemm1<<<(NNODES + 127) / 128, 256>>>(x, W1, att_src1, att_dst1,
                                           (__half2*)out, NNODES);
    k_edge1<<<(NNODES * 32 + 255) / 256, 256>>>((const __half2*)out, b1, NNODES);

    // layer 2 (no GEMM2, no att2 kernel: both fused)
    k_edge2<<<(NNODES * 32 + 255) / 256, 256>>>(W2, b2, out, NNODES);
}

// round 16
// speedup vs baseline: 1.4683x; 1.4683x over previous
#include <cuda_runtime.h>
#include <cuda_fp16.h>
#include <mma.h>

using namespace nvcuda;

// ---------------------------------------------------------------------------
// GAT (2-layer, PyG-style) on B200 (sm_100a). Pristine module form; total
// __device__ data ~12.2 MB. Layer-2 GEMM folded through the segment-sum.
//
// R16 = R14 (212.7 us, measured good) + two zero-risk launch eliminations:
//  * k_init_deg removed: g_deg re-zeroed in k_scan_add (after its only
//    reader k_scan_local; module-load zero covers the first run).
//  * k_vs folded into k_scan_add (block 0, threads 0..63).
// Edge kernels and CSR scan structure are EXACTLY R14 (the R15 edge-loop
// rewrite regressed and is abandoned).
// ---------------------------------------------------------------------------

#define NNODES 50000
#define NEDGES 1600000
#define SLOPE  0.2f
#define EPSV   1e-16f

// ------------------------- scratch (static device) --------------------------
__device__ unsigned short g_csr[NEDGES];        // 3.2 MB
__device__ __half2        g_a1[NNODES * 8];     // (as,ad) per head, 1.6 MB
__device__ __half2        g_hin[NNODES * 32];   // hin fp16 [N,64], 6.4 MB
__device__ float          g_as2[NNODES];        // 0.2 MB
__device__ float          g_ad2[NNODES];        // 0.2 MB
__device__ int            g_row_ptr[NNODES + 1];
__device__ int            g_deg[NNODES];        // zero at load; re-zeroed per run
__device__ int            g_pos[NNODES];
__device__ int            g_bsum[64];
__device__ int            g_boff[64];
__device__ float          g_vs[64];
__device__ float          g_vd[64];

__device__ __forceinline__ float lrelu(float v) { return fmaxf(v, SLOPE * v); }

// ------------------------------ CSR build -----------------------------------
__global__ void __launch_bounds__(256) k_count(const int* __restrict__ dst, int n) {
    int e = blockIdx.x * blockDim.x + threadIdx.x;
    if (e < n) atomicAdd(&g_deg[dst[e]], 1);
}

#define SCAN_B 1024
__global__ void __launch_bounds__(SCAN_B) k_scan_local(int n) {
    __shared__ int s[SCAN_B];
    int tid = threadIdx.x;
    int i = blockIdx.x * SCAN_B + tid;
    int v = (i < n) ? g_deg[i] : 0;
    s[tid] = v;
    __syncthreads();
#pragma unroll
    for (int off = 1; off < SCAN_B; off <<= 1) {
        int t = (tid >= off) ? s[tid - off] : 0;
        __syncthreads();
        s[tid] += t;
        __syncthreads();
    }
    if (i < n) g_row_ptr[i] = s[tid] - v;
    if (tid == SCAN_B - 1) g_bsum[blockIdx.x] = s[tid];
}

__global__ void __launch_bounds__(64) k_scan_block(int nblk) {
    __shared__ int s[64];
    int i = threadIdx.x;
    int v = (i < nblk) ? g_bsum[i] : 0;
    s[i] = v;
    __syncthreads();
#pragma unroll
    for (int off = 1; off < 64; off <<= 1) {
        int t = (i >= off) ? s[i - off] : 0;
        __syncthreads();
        s[i] += t;
        __syncthreads();
    }
    if (i < nblk) g_boff[i] = s[i] - v;
}

// + re-zeroes g_deg (only reader, k_scan_local, already ran)
// + block 0 threads 0..63 compute vs/vd = W2 @ att2 vectors
__global__ void __launch_bounds__(SCAN_B) k_scan_add(
    int n, const float* __restrict__ W2,
    const float* __restrict__ att_src2, const float* __restrict__ att_dst2) {
    int tid = threadIdx.x;
    int i = blockIdx.x * SCAN_B + tid;
    if (i < n) {
        int r = g_row_ptr[i] + g_boff[blockIdx.x];
        g_row_ptr[i] = r;
        g_pos[i] = r;
        g_deg[i] = 0;                    // reset for next run (replay-safe)
    }
    if (i == 0) g_row_ptr[NNODES] = NEDGES;
    if (blockIdx.x == 0 && tid < 64) {
        float vs = 0.f, vd = 0.f;
        for (int j = 0; j < 64; j++) {
            float w = W2[tid * 64 + j];
            vs += w * att_src2[j];
            vd += w * att_dst2[j];
        }
        g_vs[tid] = vs;
        g_vd[tid] = vd;
    }
}

__global__ void __launch_bounds__(256) k_scatter(const int* __restrict__ src,
                                                 const int* __restrict__ dst, int n) {
    int e = blockIdx.x * blockDim.x + threadIdx.x;
    if (e < n) {
        int d = dst[e];
        int p = atomicAdd(&g_pos[d], 1);
        g_csr[p] = (unsigned short)src[e];
    }
}

// --------------- GEMM1 (wmma fp16 tensor cores) + fused att1 -----------------
struct GemmAB {
    __half As[128][40];     // 128x32 + pad8
    __half Bs[32][72];      // 32x64 + pad8
};
union GemmSmem {
    GemmAB ab;
    float  Cs[128][68];     // 128x64 + pad4
};

__global__ void __launch_bounds__(256) k_gemm1(const float* __restrict__ A,
                                               const float* __restrict__ B,
                                               const float* __restrict__ att_src,
                                               const float* __restrict__ att_dst,
                                               __half2* __restrict__ C, int M) {
    const int block_row = blockIdx.x * 128;
    if (block_row >= M) return;
    __shared__ GemmSmem sm;
    __shared__ float ss[64], sd[64];
    const int tid = threadIdx.x;
    if (tid < 64) { ss[tid] = att_src[tid]; sd[tid] = att_dst[tid]; }

    const int wid = tid >> 5;
    const int warp_m = wid & 3;
    const int warp_n = wid >> 2;

    wmma::fragment<wmma::accumulator, 16, 16, 16, float> acc[2][2];
#pragma unroll
    for (int i = 0; i < 2; i++)
#pragma unroll
        for (int j = 0; j < 2; j++) wmma::fill_fragment(acc[i][j], 0.f);

    for (int k0 = 0; k0 < 256; k0 += 32) {
#pragma unroll
        for (int it = 0; it < 4; it++) {
            int f4 = it * 256 + tid;
            int r = f4 >> 3;
            int c4 = (f4 & 7) * 4;
            int gr = block_row + r;
            float4 v = make_float4(0.f, 0.f, 0.f, 0.f);
            if (gr < M) v = *(const float4*)(A + (size_t)gr * 256 + k0 + c4);
            sm.ab.As[r][c4 + 0] = __float2half_rn(v.x);
            sm.ab.As[r][c4 + 1] = __float2half_rn(v.y);
            sm.ab.As[r][c4 + 2] = __float2half_rn(v.z);
            sm.ab.As[r][c4 + 3] = __float2half_rn(v.w);
        }
#pragma unroll
        for (int it = 0; it < 2; it++) {
            int f4 = it * 256 + tid;
            int r = f4 >> 4;
            int c4 = (f4 & 15) * 4;
            float4 v = *(const float4*)(B + (size_t)(k0 + r) * 64 + c4);
            sm.ab.Bs[r][c4 + 0] = __float2half_rn(v.x);
            sm.ab.Bs[r][c4 + 1] = __float2half_rn(v.y);
            sm.ab.Bs[r][c4 + 2] = __float2half_rn(v.z);
            sm.ab.Bs[r][c4 + 3] = __float2half_rn(v.w);
        }
        __syncthreads();
#pragma unroll
        for (int kf = 0; kf < 2; kf++) {
            wmma::fragment<wmma::matrix_a, 16, 16, 16, __half, wmma::row_major> a_frag[2];
            wmma::fragment<wmma::matrix_b, 16, 16, 16, __half, wmma::row_major> b_frag[2];
#pragma unroll
            for (int fm = 0; fm < 2; fm++)
                wmma::load_matrix_sync(a_frag[fm],
                    &sm.ab.As[warp_m * 32 + fm * 16][kf * 16], 40);
#pragma unroll
            for (int fn = 0; fn < 2; fn++)
                wmma::load_matrix_sync(b_frag[fn],
                    &sm.ab.Bs[kf * 16][warp_n * 32 + fn * 16], 72);
#pragma unroll
            for (int fm = 0; fm < 2; fm++)
#pragma unroll
                for (int fn = 0; fn < 2; fn++)
                    wmma::mma_sync(acc[fm][fn], a_frag[fm], b_frag[fn], acc[fm][fn]);
        }
        __syncthreads();
    }

#pragma unroll
    for (int fm = 0; fm < 2; fm++)
#pragma unroll
        for (int fn = 0; fn < 2; fn++)
            wmma::store_matrix_sync(&sm.Cs[warp_m * 32 + fm * 16][warp_n * 32 + fn * 16],
                                    acc[fm][fn], 68, wmma::mem_row_major);
    __syncthreads();

    if (tid < 128) {
        int gr = block_row + tid;
        if (gr < M) {
            const float* row = sm.Cs[tid];
#pragma unroll
            for (int c = 0; c < 32; c++)
                C[(size_t)gr * 32 + c] = __floats2half2_rn(row[2 * c], row[2 * c + 1]);
#pragma unroll
            for (int h = 0; h < 8; h++) {
                float as = 0.f, ad = 0.f;
#pragma unroll
                for (int j = 0; j < 8; j++) {
                    float v = row[h * 8 + j];
                    as += v * ss[h * 8 + j];
                    ad += v * sd[h * 8 + j];
                }
                g_a1[(size_t)gr * 8 + h] = __floats2half2_rn(as, ad);
            }
        }
    }
}

// ------- layer 1: ONE-pass softmax-agg + ELU + fused layer-2 att dots -------
__global__ void __launch_bounds__(256) k_edge1(const __half2* __restrict__ h1,
                                               const float* __restrict__ b1, int n) {
    int wid = (blockIdx.x * blockDim.x + threadIdx.x) >> 5;
    int lane = threadIdx.x & 31;
    if (wid >= n) return;
    const int d = wid;
    const int beg = g_row_ptr[d];
    const int end = g_row_ptr[d + 1];
    const int h0 = lane >> 2;
    const int f0 = 2 * lane;

    float2 pd = __half22float2(g_a1[(size_t)d * 8 + h0]);
    const float ad_h = pd.y;
    const float aself = lrelu(pd.x + ad_h);

    float acc0 = 0.f, acc1 = 0.f, sden = 0.f;
    int e = beg;
    for (; e + 4 <= end; e += 4) {
        int s0 = g_csr[e], s1 = g_csr[e + 1], s2 = g_csr[e + 2], s3 = g_csr[e + 3];
        float2 pa0 = __half22float2(g_a1[(size_t)s0 * 8 + h0]);
        float2 pa1 = __half22float2(g_a1[(size_t)s1 * 8 + h0]);
        float2 pa2 = __half22float2(g_a1[(size_t)s2 * 8 + h0]);
        float2 pa3 = __half22float2(g_a1[(size_t)s3 * 8 + h0]);
        float2 hv0 = __half22float2(h1[(size_t)s0 * 32 + lane]);
        float2 hv1 = __half22float2(h1[(size_t)s1 * 32 + lane]);
        float2 hv2 = __half22float2(h1[(size_t)s2 * 32 + lane]);
        float2 hv3 = __half22float2(h1[(size_t)s3 * 32 + lane]);
        float w0 = __expf(lrelu(pa0.x + ad_h));
        float w1 = __expf(lrelu(pa1.x + ad_h));
        float w2 = __expf(lrelu(pa2.x + ad_h));
        float w3 = __expf(lrelu(pa3.x + ad_h));
        sden += (w0 + w1) + (w2 + w3);
        acc0 += hv0.x * w0 + hv1.x * w1 + hv2.x * w2 + hv3.x * w3;
        acc1 += hv0.y * w0 + hv1.y * w1 + hv2.y * w2 + hv3.y * w3;
    }
    for (; e < end; e++) {
        int s = g_csr[e];
        float2 pa = __half22float2(g_a1[(size_t)s * 8 + h0]);
        float w = __expf(lrelu(pa.x + ad_h));
        sden += w;
        float2 hv = __half22float2(h1[(size_t)s * 32 + lane]);
        acc0 += hv.x * w;
        acc1 += hv.y * w;
    }
    {   // self loop
        float w = __expf(aself);
        sden += w;
        float2 hv = __half22float2(h1[(size_t)d * 32 + lane]);
        acc0 += hv.x * w;
        acc1 += hv.y * w;
    }
    float rinv = 1.f / (sden + EPSV);
    float2 bb = *(const float2*)(b1 + f0);
    float v0 = acc0 * rinv + bb.x;
    float v1 = acc1 * rinv + bb.y;
    v0 = (v0 > 0.f) ? v0 : (__expf(v0) - 1.f);   // ELU
    v1 = (v1 > 0.f) ? v1 : (__expf(v1) - 1.f);
    g_hin[(size_t)d * 32 + lane] = __floats2half2_rn(v0, v1);

    float ps = v0 * g_vs[f0] + v1 * g_vs[f0 + 1];
    float pdd = v0 * g_vd[f0] + v1 * g_vd[f0 + 1];
#pragma unroll
    for (int off = 16; off; off >>= 1) {
        ps  += __shfl_xor_sync(0xffffffffu, ps, off);
        pdd += __shfl_xor_sync(0xffffffffu, pdd, off);
    }
    if (lane == 0) {
        g_as2[d] = ps;
        g_ad2[d] = pdd;
    }
}

// -- layer 2: ONE-pass softmax-agg over hin, fused @W2 + b2 + log_softmax ----
__global__ void __launch_bounds__(256) k_edge2(const float* __restrict__ W2,
                                               const float* __restrict__ b2,
                                               float* __restrict__ out, int n) {
    __shared__ float2 W2s[64 * 32];
    __shared__ float  b2s[64];
    __shared__ float  sagg[8][64];
    int tid = threadIdx.x;
    {
        const float2* w2v = (const float2*)W2;
#pragma unroll
        for (int it = 0; it < 8; it++) W2s[tid + it * 256] = w2v[tid + it * 256];
        if (tid < 64) b2s[tid] = b2[tid];
    }
    __syncthreads();

    int wid = (blockIdx.x * blockDim.x + tid) >> 5;
    int wloc = (tid >> 5);
    int lane = tid & 31;
    if (wid >= n) return;
    const int d = wid;
    const int beg = g_row_ptr[d];
    const int end = g_row_ptr[d + 1];
    const float ad2 = g_ad2[d];
    const float aself = lrelu(g_as2[d] + ad2);

    float acc0 = 0.f, acc1 = 0.f, sden = 0.f;
    int e = beg;
    for (; e + 4 <= end; e += 4) {
        int s0 = g_csr[e], s1 = g_csr[e + 1], s2 = g_csr[e + 2], s3 = g_csr[e + 3];
        float a0 = g_as2[s0], a1 = g_as2[s1], a2 = g_as2[s2], a3 = g_as2[s3];
        float2 f0v = __half22float2(g_hin[(size_t)s0 * 32 + lane]);
        float2 f1v = __half22float2(g_hin[(size_t)s1 * 32 + lane]);
        float2 f2v = __half22float2(g_hin[(size_t)s2 * 32 + lane]);
        float2 f3v = __half22float2(g_hin[(size_t)s3 * 32 + lane]);
        float w0 = __expf(lrelu(a0 + ad2));
        float w1 = __expf(lrelu(a1 + ad2));
        float w2 = __expf(lrelu(a2 + ad2));
        float w3 = __expf(lrelu(a3 + ad2));
        sden += (w0 + w1) + (w2 + w3);
        acc0 += f0v.x * w0 + f1v.x * w1 + f2v.x * w2 + f3v.x * w3;
        acc1 += f0v.y * w0 + f1v.y * w1 + f2v.y * w2 + f3v.y * w3;
    }
    for (; e < end; e++) {
        int s = g_csr[e];
        float w = __expf(lrelu(g_as2[s] + ad2));
        sden += w;
        float2 f = __half22float2(g_hin[(size_t)s * 32 + lane]);
        acc0 += f.x * w;
        acc1 += f.y * w;
    }
    {
        float w = __expf(aself);
        sden += w;
        float2 f = __half22float2(g_hin[(size_t)d * 32 + lane]);
        acc0 += f.x * w;
        acc1 += f.y * w;
    }
    float rinv = 1.f / (sden + EPSV);
    acc0 *= rinv;
    acc1 *= rinv;

    sagg[wloc][2 * lane]     = acc0;
    sagg[wloc][2 * lane + 1] = acc1;
    __syncwarp();
    float o0 = b2s[2 * lane];
    float o1 = b2s[2 * lane + 1];
#pragma unroll
    for (int k = 0; k < 64; k++) {
        float a = sagg[wloc][k];
        float2 w2 = W2s[k * 32 + lane];
        o0 += a * w2.x;
        o1 += a * w2.y;
    }

    float mx = fmaxf(o0, o1);
#pragma unroll
    for (int off = 16; off; off >>= 1)
        mx = fmaxf(mx, __shfl_xor_sync(0xffffffffu, mx, off));
    float se = __expf(o0 - mx) + __expf(o1 - mx);
#pragma unroll
    for (int off = 16; off; off >>= 1)
        se += __shfl_xor_sync(0xffffffffu, se, off);
    float l = mx + logf(se);
    float2* out2 = (float2*)(out + (size_t)d * 64);
    out2[lane] = make_float2(o0 - l, o1 - l);
}

// ------------------------------ launcher ------------------------------------
extern "C" void kernel_launch(void* const* d_in, const int* in_sizes, int n_in,
                              void* d_out, int out_size) {
    const float* x        = (const float*)d_in[0];
    const int*   ei       = (const int*)d_in[1];
    const float* W1       = (const float*)d_in[2];
    const float* att_src1 = (const float*)d_in[3];
    const float* att_dst1 = (const float*)d_in[4];
    const float* b1       = (const float*)d_in[5];
    const float* W2       = (const float*)d_in[6];
    const float* att_src2 = (const float*)d_in[7];
    const float* att_dst2 = (const float*)d_in[8];
    const float* b2       = (const float*)d_in[9];
    float* out = (float*)d_out;

    const int* src = ei;
    const int* dst = ei + NEDGES;

    const int nblk_scan = (NNODES + SCAN_B - 1) / SCAN_B;   // 49

    // CSR build (g_deg zero at module load; re-zeroed by k_scan_add each run)
    k_count<<<(NEDGES + 255) / 256, 256>>>(dst, NEDGES);
    k_scan_local<<<nblk_scan, SCAN_B>>>(NNODES);
    k_scan_block<<<1, 64>>>(nblk_scan);
    k_scan_add<<<nblk_scan, SCAN_B>>>(NNODES, W2, att_src2, att_dst2);
    k_scatter<<<(NEDGES + 255) / 256, 256>>>(src, dst, NEDGES);

    // layer 1: h1(fp16) -> d_out, att1 dots fused -> g_a1
    k_gemm1<<<(NNODES + 127) / 128, 256>>>(x, W1, att_src1, att_dst1,
                                           (__half2*)out, NNODES);
    k_edge1<<<(NNODES * 32 + 255) / 256, 256>>>((const __half2*)out, b1, NNODES);

    // layer 2 (no GEMM2, no att2 kernel: both fused)
    k_edge2<<<(NNODES * 32 + 255) / 256, 256>>>(W2, b2, out, NNODES);
}

// round 17
// speedup vs baseline: 1.7241x; 1.1742x over previous
#include <cuda_runtime.h>
#include <cuda_fp16.h>
#include <mma.h>

using namespace nvcuda;

// ---------------------------------------------------------------------------
// GAT (2-layer, PyG-style) on B200 (sm_100a). Pristine module form; total
// __device__ data ~12.2 MB. Layer-2 GEMM folded through the segment-sum.
//
// R17 vs R16 (209.2 us): edge kernels use HALF-WARP (16 lanes) per node,
// 4 features per lane via single 8B loads -> LDG instructions and MUFU ops
// per edge halved; two nodes per warp. All reductions use offset<16 XOR
// shuffles (closed within each half-warp). Everything else identical to R16.
// ---------------------------------------------------------------------------

#define NNODES 50000
#define NEDGES 1600000
#define SLOPE  0.2f
#define EPSV   1e-16f

// ------------------------- scratch (static device) --------------------------
__device__ unsigned short g_csr[NEDGES];        // 3.2 MB
__device__ __half2        g_a1[NNODES * 8];     // (as,ad) per head, 1.6 MB
__device__ __half2        g_hin[NNODES * 32];   // hin fp16 [N,64], 6.4 MB
__device__ float          g_as2[NNODES];        // 0.2 MB
__device__ float          g_ad2[NNODES];        // 0.2 MB
__device__ int            g_row_ptr[NNODES + 1];
__device__ int            g_deg[NNODES];        // zero at load; re-zeroed per run
__device__ int            g_pos[NNODES];
__device__ int            g_bsum[64];
__device__ int            g_boff[64];
__device__ float          g_vs[64];
__device__ float          g_vd[64];

__device__ __forceinline__ float lrelu(float v) { return fmaxf(v, SLOPE * v); }

// ------------------------------ CSR build -----------------------------------
__global__ void __launch_bounds__(256) k_count(const int* __restrict__ dst, int n) {
    int e = blockIdx.x * blockDim.x + threadIdx.x;
    if (e < n) atomicAdd(&g_deg[dst[e]], 1);
}

#define SCAN_B 1024
__global__ void __launch_bounds__(SCAN_B) k_scan_local(int n) {
    __shared__ int s[SCAN_B];
    int tid = threadIdx.x;
    int i = blockIdx.x * SCAN_B + tid;
    int v = (i < n) ? g_deg[i] : 0;
    s[tid] = v;
    __syncthreads();
#pragma unroll
    for (int off = 1; off < SCAN_B; off <<= 1) {
        int t = (tid >= off) ? s[tid - off] : 0;
        __syncthreads();
        s[tid] += t;
        __syncthreads();
    }
    if (i < n) g_row_ptr[i] = s[tid] - v;
    if (tid == SCAN_B - 1) g_bsum[blockIdx.x] = s[tid];
}

__global__ void __launch_bounds__(64) k_scan_block(int nblk) {
    __shared__ int s[64];
    int i = threadIdx.x;
    int v = (i < nblk) ? g_bsum[i] : 0;
    s[i] = v;
    __syncthreads();
#pragma unroll
    for (int off = 1; off < 64; off <<= 1) {
        int t = (i >= off) ? s[i - off] : 0;
        __syncthreads();
        s[i] += t;
        __syncthreads();
    }
    if (i < nblk) g_boff[i] = s[i] - v;
}

__global__ void __launch_bounds__(SCAN_B) k_scan_add(
    int n, const float* __restrict__ W2,
    const float* __restrict__ att_src2, const float* __restrict__ att_dst2) {
    int tid = threadIdx.x;
    int i = blockIdx.x * SCAN_B + tid;
    if (i < n) {
        int r = g_row_ptr[i] + g_boff[blockIdx.x];
        g_row_ptr[i] = r;
        g_pos[i] = r;
        g_deg[i] = 0;                    // reset for next run (replay-safe)
    }
    if (i == 0) g_row_ptr[NNODES] = NEDGES;
    if (blockIdx.x == 0 && tid < 64) {
        float vs = 0.f, vd = 0.f;
        for (int j = 0; j < 64; j++) {
            float w = W2[tid * 64 + j];
            vs += w * att_src2[j];
            vd += w * att_dst2[j];
        }
        g_vs[tid] = vs;
        g_vd[tid] = vd;
    }
}

__global__ void __launch_bounds__(256) k_scatter(const int* __restrict__ src,
                                                 const int* __restrict__ dst, int n) {
    int e = blockIdx.x * blockDim.x + threadIdx.x;
    if (e < n) {
        int d = dst[e];
        int p = atomicAdd(&g_pos[d], 1);
        g_csr[p] = (unsigned short)src[e];
    }
}

// --------------- GEMM1 (wmma fp16 tensor cores) + fused att1 -----------------
struct GemmAB {
    __half As[128][40];     // 128x32 + pad8
    __half Bs[32][72];      // 32x64 + pad8
};
union GemmSmem {
    GemmAB ab;
    float  Cs[128][68];     // 128x64 + pad4
};

__global__ void __launch_bounds__(256) k_gemm1(const float* __restrict__ A,
                                               const float* __restrict__ B,
                                               const float* __restrict__ att_src,
                                               const float* __restrict__ att_dst,
                                               __half2* __restrict__ C, int M) {
    const int block_row = blockIdx.x * 128;
    if (block_row >= M) return;
    __shared__ GemmSmem sm;
    __shared__ float ss[64], sd[64];
    const int tid = threadIdx.x;
    if (tid < 64) { ss[tid] = att_src[tid]; sd[tid] = att_dst[tid]; }

    const int wid = tid >> 5;
    const int warp_m = wid & 3;
    const int warp_n = wid >> 2;

    wmma::fragment<wmma::accumulator, 16, 16, 16, float> acc[2][2];
#pragma unroll
    for (int i = 0; i < 2; i++)
#pragma unroll
        for (int j = 0; j < 2; j++) wmma::fill_fragment(acc[i][j], 0.f);

    for (int k0 = 0; k0 < 256; k0 += 32) {
#pragma unroll
        for (int it = 0; it < 4; it++) {
            int f4 = it * 256 + tid;
            int r = f4 >> 3;
            int c4 = (f4 & 7) * 4;
            int gr = block_row + r;
            float4 v = make_float4(0.f, 0.f, 0.f, 0.f);
            if (gr < M) v = *(const float4*)(A + (size_t)gr * 256 + k0 + c4);
            sm.ab.As[r][c4 + 0] = __float2half_rn(v.x);
            sm.ab.As[r][c4 + 1] = __float2half_rn(v.y);
            sm.ab.As[r][c4 + 2] = __float2half_rn(v.z);
            sm.ab.As[r][c4 + 3] = __float2half_rn(v.w);
        }
#pragma unroll
        for (int it = 0; it < 2; it++) {
            int f4 = it * 256 + tid;
            int r = f4 >> 4;
            int c4 = (f4 & 15) * 4;
            float4 v = *(const float4*)(B + (size_t)(k0 + r) * 64 + c4);
            sm.ab.Bs[r][c4 + 0] = __float2half_rn(v.x);
            sm.ab.Bs[r][c4 + 1] = __float2half_rn(v.y);
            sm.ab.Bs[r][c4 + 2] = __float2half_rn(v.z);
            sm.ab.Bs[r][c4 + 3] = __float2half_rn(v.w);
        }
        __syncthreads();
#pragma unroll
        for (int kf = 0; kf < 2; kf++) {
            wmma::fragment<wmma::matrix_a, 16, 16, 16, __half, wmma::row_major> a_frag[2];
            wmma::fragment<wmma::matrix_b, 16, 16, 16, __half, wmma::row_major> b_frag[2];
#pragma unroll
            for (int fm = 0; fm < 2; fm++)
                wmma::load_matrix_sync(a_frag[fm],
                    &sm.ab.As[warp_m * 32 + fm * 16][kf * 16], 40);
#pragma unroll
            for (int fn = 0; fn < 2; fn++)
                wmma::load_matrix_sync(b_frag[fn],
                    &sm.ab.Bs[kf * 16][warp_n * 32 + fn * 16], 72);
#pragma unroll
            for (int fm = 0; fm < 2; fm++)
#pragma unroll
                for (int fn = 0; fn < 2; fn++)
                    wmma::mma_sync(acc[fm][fn], a_frag[fm], b_frag[fn], acc[fm][fn]);
        }
        __syncthreads();
    }

#pragma unroll
    for (int fm = 0; fm < 2; fm++)
#pragma unroll
        for (int fn = 0; fn < 2; fn++)
            wmma::store_matrix_sync(&sm.Cs[warp_m * 32 + fm * 16][warp_n * 32 + fn * 16],
                                    acc[fm][fn], 68, wmma::mem_row_major);
    __syncthreads();

    if (tid < 128) {
        int gr = block_row + tid;
        if (gr < M) {
            const float* row = sm.Cs[tid];
#pragma unroll
            for (int c = 0; c < 32; c++)
                C[(size_t)gr * 32 + c] = __floats2half2_rn(row[2 * c], row[2 * c + 1]);
#pragma unroll
            for (int h = 0; h < 8; h++) {
                float as = 0.f, ad = 0.f;
#pragma unroll
                for (int j = 0; j < 8; j++) {
                    float v = row[h * 8 + j];
                    as += v * ss[h * 8 + j];
                    ad += v * sd[h * 8 + j];
                }
                g_a1[(size_t)gr * 8 + h] = __floats2half2_rn(as, ad);
            }
        }
    }
}

// ------- layer 1: HALF-WARP per node, 4 features/lane, one-pass softmax -----
__global__ void __launch_bounds__(256) k_edge1(const __half2* __restrict__ h1,
                                               const float* __restrict__ b1, int n) {
    int grp = (blockIdx.x * blockDim.x + threadIdx.x) >> 4;   // 16-lane group
    int sl = threadIdx.x & 15;
    if (grp >= n) return;
    const int d = grp;
    const int beg = g_row_ptr[d];
    const int end = g_row_ptr[d + 1];
    const int h0 = sl >> 1;              // features 4sl..4sl+3 share head sl>>1
    const int fb = 4 * sl;

    float2 pdz = __half22float2(g_a1[(size_t)d * 8 + h0]);
    const float ad_h = pdz.y;
    const float aself = lrelu(pdz.x + ad_h);

    float acc0 = 0.f, acc1 = 0.f, acc2 = 0.f, acc3 = 0.f, sden = 0.f;
    int e = beg;
    for (; e + 4 <= end; e += 4) {
        int s0 = g_csr[e], s1 = g_csr[e + 1], s2 = g_csr[e + 2], s3 = g_csr[e + 3];
        float pa0 = __half22float2(g_a1[(size_t)s0 * 8 + h0]).x;
        float pa1 = __half22float2(g_a1[(size_t)s1 * 8 + h0]).x;
        float pa2 = __half22float2(g_a1[(size_t)s2 * 8 + h0]).x;
        float pa3 = __half22float2(g_a1[(size_t)s3 * 8 + h0]).x;
        uint2 u0 = *(const uint2*)&h1[(size_t)s0 * 32 + 2 * sl];
        uint2 u1 = *(const uint2*)&h1[(size_t)s1 * 32 + 2 * sl];
        uint2 u2 = *(const uint2*)&h1[(size_t)s2 * 32 + 2 * sl];
        uint2 u3 = *(const uint2*)&h1[(size_t)s3 * 32 + 2 * sl];
        float w0 = __expf(lrelu(pa0 + ad_h));
        float w1 = __expf(lrelu(pa1 + ad_h));
        float w2 = __expf(lrelu(pa2 + ad_h));
        float w3 = __expf(lrelu(pa3 + ad_h));
        sden += (w0 + w1) + (w2 + w3);
        float2 a0f = __half22float2(*(__half2*)&u0.x), a0g = __half22float2(*(__half2*)&u0.y);
        float2 a1f = __half22float2(*(__half2*)&u1.x), a1g = __half22float2(*(__half2*)&u1.y);
        float2 a2f = __half22float2(*(__half2*)&u2.x), a2g = __half22float2(*(__half2*)&u2.y);
        float2 a3f = __half22float2(*(__half2*)&u3.x), a3g = __half22float2(*(__half2*)&u3.y);
        acc0 += a0f.x * w0 + a1f.x * w1 + a2f.x * w2 + a3f.x * w3;
        acc1 += a0f.y * w0 + a1f.y * w1 + a2f.y * w2 + a3f.y * w3;
        acc2 += a0g.x * w0 + a1g.x * w1 + a2g.x * w2 + a3g.x * w3;
        acc3 += a0g.y * w0 + a1g.y * w1 + a2g.y * w2 + a3g.y * w3;
    }
    for (; e < end; e++) {
        int s = g_csr[e];
        float pa = __half22float2(g_a1[(size_t)s * 8 + h0]).x;
        float w = __expf(lrelu(pa + ad_h));
        sden += w;
        uint2 u = *(const uint2*)&h1[(size_t)s * 32 + 2 * sl];
        float2 f = __half22float2(*(__half2*)&u.x), g = __half22float2(*(__half2*)&u.y);
        acc0 += f.x * w; acc1 += f.y * w; acc2 += g.x * w; acc3 += g.y * w;
    }
    {   // self loop
        float w = __expf(aself);
        sden += w;
        uint2 u = *(const uint2*)&h1[(size_t)d * 32 + 2 * sl];
        float2 f = __half22float2(*(__half2*)&u.x), g = __half22float2(*(__half2*)&u.y);
        acc0 += f.x * w; acc1 += f.y * w; acc2 += g.x * w; acc3 += g.y * w;
    }
    float rinv = 1.f / (sden + EPSV);
    float4 bb = *(const float4*)(b1 + fb);
    float v0 = acc0 * rinv + bb.x;
    float v1 = acc1 * rinv + bb.y;
    float v2 = acc2 * rinv + bb.z;
    float v3 = acc3 * rinv + bb.w;
    v0 = (v0 > 0.f) ? v0 : (__expf(v0) - 1.f);
    v1 = (v1 > 0.f) ? v1 : (__expf(v1) - 1.f);
    v2 = (v2 > 0.f) ? v2 : (__expf(v2) - 1.f);
    v3 = (v3 > 0.f) ? v3 : (__expf(v3) - 1.f);
    {
        __half2 p0 = __floats2half2_rn(v0, v1);
        __half2 p1 = __floats2half2_rn(v2, v3);
        uint2 u;
        u.x = *(unsigned*)&p0;
        u.y = *(unsigned*)&p1;
        *(uint2*)&g_hin[(size_t)d * 32 + 2 * sl] = u;
    }

    // fused layer-2 attention dots (16-lane XOR reduce stays in half-warp)
    float4 vsv = *(const float4*)&g_vs[fb];
    float4 vdv = *(const float4*)&g_vd[fb];
    float ps = v0 * vsv.x + v1 * vsv.y + v2 * vsv.z + v3 * vsv.w;
    float pdd = v0 * vdv.x + v1 * vdv.y + v2 * vdv.z + v3 * vdv.w;
#pragma unroll
    for (int off = 8; off; off >>= 1) {
        ps  += __shfl_xor_sync(0xffffffffu, ps, off);
        pdd += __shfl_xor_sync(0xffffffffu, pdd, off);
    }
    if (sl == 0) {
        g_as2[d] = ps;
        g_ad2[d] = pdd;
    }
}

// -- layer 2: HALF-WARP per node, fused @W2 + b2 + log_softmax ---------------
__global__ void __launch_bounds__(256) k_edge2(const float* __restrict__ W2,
                                               const float* __restrict__ b2,
                                               float* __restrict__ out, int n) {
    __shared__ float4 W2s4[64 * 16];        // W2[k][4c..4c+3] at [k*16+c]
    __shared__ float4 b2s4[16];
    __shared__ float  sagg[16][64];         // per 16-lane group
    int tid = threadIdx.x;
    {
        const float4* w2v = (const float4*)W2;
#pragma unroll
        for (int it = 0; it < 4; it++) W2s4[tid + it * 256] = w2v[tid + it * 256];
        if (tid < 16) b2s4[tid] = ((const float4*)b2)[tid];
    }
    __syncthreads();

    int grp = (blockIdx.x * blockDim.x + tid) >> 4;
    int gloc = tid >> 4;                    // 0..15 group within block
    int sl = tid & 15;
    if (grp >= n) return;
    const int d = grp;
    const int beg = g_row_ptr[d];
    const int end = g_row_ptr[d + 1];
    const float ad2 = g_ad2[d];
    const float aself = lrelu(g_as2[d] + ad2);

    float acc0 = 0.f, acc1 = 0.f, acc2 = 0.f, acc3 = 0.f, sden = 0.f;
    int e = beg;
    for (; e + 4 <= end; e += 4) {
        int s0 = g_csr[e], s1 = g_csr[e + 1], s2 = g_csr[e + 2], s3 = g_csr[e + 3];
        float a0 = g_as2[s0], a1 = g_as2[s1], a2 = g_as2[s2], a3 = g_as2[s3];
        uint2 u0 = *(const uint2*)&g_hin[(size_t)s0 * 32 + 2 * sl];
        uint2 u1 = *(const uint2*)&g_hin[(size_t)s1 * 32 + 2 * sl];
        uint2 u2 = *(const uint2*)&g_hin[(size_t)s2 * 32 + 2 * sl];
        uint2 u3 = *(const uint2*)&g_hin[(size_t)s3 * 32 + 2 * sl];
        float w0 = __expf(lrelu(a0 + ad2));
        float w1 = __expf(lrelu(a1 + ad2));
        float w2 = __expf(lrelu(a2 + ad2));
        float w3 = __expf(lrelu(a3 + ad2));
        sden += (w0 + w1) + (w2 + w3);
        float2 f0 = __half22float2(*(__half2*)&u0.x), g0 = __half22float2(*(__half2*)&u0.y);
        float2 f1 = __half22float2(*(__half2*)&u1.x), g1 = __half22float2(*(__half2*)&u1.y);
        float2 f2 = __half22float2(*(__half2*)&u2.x), g2 = __half22float2(*(__half2*)&u2.y);
        float2 f3 = __half22float2(*(__half2*)&u3.x), g3 = __half22float2(*(__half2*)&u3.y);
        acc0 += f0.x * w0 + f1.x * w1 + f2.x * w2 + f3.x * w3;
        acc1 += f0.y * w0 + f1.y * w1 + f2.y * w2 + f3.y * w3;
        acc2 += g0.x * w0 + g1.x * w1 + g2.x * w2 + g3.x * w3;
        acc3 += g0.y * w0 + g1.y * w1 + g2.y * w2 + g3.y * w3;
    }
    for (; e < end; e++) {
        int s = g_csr[e];
        float w = __expf(lrelu(g_as2[s] + ad2));
        sden += w;
        uint2 u = *(const uint2*)&g_hin[(size_t)s * 32 + 2 * sl];
        float2 f = __half22float2(*(__half2*)&u.x), g = __half22float2(*(__half2*)&u.y);
        acc0 += f.x * w; acc1 += f.y * w; acc2 += g.x * w; acc3 += g.y * w;
    }
    {
        float w = __expf(aself);
        sden += w;
        uint2 u = *(const uint2*)&g_hin[(size_t)d * 32 + 2 * sl];
        float2 f = __half22float2(*(__half2*)&u.x), g = __half22float2(*(__half2*)&u.y);
        acc0 += f.x * w; acc1 += f.y * w; acc2 += g.x * w; acc3 += g.y * w;
    }
    float rinv = 1.f / (sden + EPSV);

    // stage agg for the matvec
    float* sa = sagg[gloc];
    sa[4 * sl + 0] = acc0 * rinv;
    sa[4 * sl + 1] = acc1 * rinv;
    sa[4 * sl + 2] = acc2 * rinv;
    sa[4 * sl + 3] = acc3 * rinv;
    __syncwarp();

    float4 bb = b2s4[sl];
    float o0 = bb.x, o1 = bb.y, o2 = bb.z, o3 = bb.w;
#pragma unroll
    for (int k = 0; k < 64; k++) {
        float a = sa[k];
        float4 w4 = W2s4[k * 16 + sl];
        o0 += a * w4.x;
        o1 += a * w4.y;
        o2 += a * w4.z;
        o3 += a * w4.w;
    }

    // log_softmax over 64 outputs (4 per lane, 16-lane reduce)
    float mx = fmaxf(fmaxf(o0, o1), fmaxf(o2, o3));
#pragma unroll
    for (int off = 8; off; off >>= 1)
        mx = fmaxf(mx, __shfl_xor_sync(0xffffffffu, mx, off));
    float se = __expf(o0 - mx) + __expf(o1 - mx) + __expf(o2 - mx) + __expf(o3 - mx);
#pragma unroll
    for (int off = 8; off; off >>= 1)
        se += __shfl_xor_sync(0xffffffffu, se, off);
    float l = mx + logf(se);
    *(float4*)&out[(size_t)d * 64 + 4 * sl] =
        make_float4(o0 - l, o1 - l, o2 - l, o3 - l);
}

// ------------------------------ launcher ------------------------------------
extern "C" void kernel_launch(void* const* d_in, const int* in_sizes, int n_in,
                              void* d_out, int out_size) {
    const float* x        = (const float*)d_in[0];
    const int*   ei       = (const int*)d_in[1];
    const float* W1       = (const float*)d_in[2];
    const float* att_src1 = (const float*)d_in[3];
    const float* att_dst1 = (const float*)d_in[4];
    const float* b1       = (const float*)d_in[5];
    const float* W2       = (const float*)d_in[6];
    const float* att_src2 = (const float*)d_in[7];
    const float* att_dst2 = (const float*)d_in[8];
    const float* b2       = (const float*)d_in[9];
    float* out = (float*)d_out;

    const int* src = ei;
    const int* dst = ei + NEDGES;

    const int nblk_scan = (NNODES + SCAN_B - 1) / SCAN_B;   // 49

    // CSR build
    k_count<<<(NEDGES + 255) / 256, 256>>>(dst, NEDGES);
    k_scan_local<<<nblk_scan, SCAN_B>>>(NNODES);
    k_scan_block<<<1, 64>>>(nblk_scan);
    k_scan_add<<<nblk_scan, SCAN_B>>>(NNODES, W2, att_src2, att_dst2);
    k_scatter<<<(NEDGES + 255) / 256, 256>>>(src, dst, NEDGES);

    // layer 1: h1(fp16) -> d_out, att1 dots fused -> g_a1
    k_gemm1<<<(NNODES + 127) / 128, 256>>>(x, W1, att_src1, att_dst1,
                                           (__half2*)out, NNODES);
    k_edge1<<<(NNODES * 16 + 255) / 256, 256>>>((const __half2*)out, b1, NNODES);

    // layer 2 (no GEMM2, no att2 kernel: both fused)
    k_edge2<<<(NNODES * 16 + 255) / 256, 256>>>(W2, b2, out, NNODES);
}